// round 13
// baseline (speedup 1.0000x reference)
#include <cuda_runtime.h>
#include <cstdint>
#include <cstddef>

// Problem constants
#define BATCH  32
#define SEQ    1024
#define INDIM  128
#define HID    512
#define LAYERS 3

// Recurrence decomposition: 16 batch-groups (2 batches) x 8 j-groups (64 cols)
#define GB 16
#define GJ 8

// ---------------- device scratch (allocation-free rule) ------------------------
__device__ float g_P[(size_t)BATCH * SEQ * HID];   // pre-activations, current layer
__device__ float g_O[(size_t)BATCH * SEQ * HID];   // layer output sequence
__device__ float g_hbuf[2][BATCH * HID];           // double-buffered hidden state
__device__ int   g_flags[GB * GJ];                 // monotonic per-CTA step flags

// ---------------- PTX helpers --------------------------------------------------
__device__ __forceinline__ unsigned long long pack2(float x, float y) {
    unsigned long long r;
    asm("mov.b64 %0, {%1, %2};" : "=l"(r) : "f"(x), "f"(y));
    return r;
}
__device__ __forceinline__ unsigned long long ffma2(unsigned long long a,
                                                    unsigned long long b,
                                                    unsigned long long c) {
    unsigned long long d;
    asm("fma.rn.f32x2 %0, %1, %2, %3;" : "=l"(d) : "l"(a), "l"(b), "l"(c));
    return d;
}
__device__ __forceinline__ float pairsum(unsigned long long p) {
    unsigned lo, hi;
    asm("mov.b64 {%0, %1}, %2;" : "=r"(lo), "=r"(hi) : "l"(p));
    return __uint_as_float(lo) + __uint_as_float(hi);
}
__device__ __forceinline__ int ld_acquire_gpu(const int* p) {
    int v;
    asm volatile("ld.global.acquire.gpu.b32 %0, [%1];" : "=r"(v) : "l"(p));
    return v;
}
// Release store on the flag: orders all prior (barrier-ordered) stores without
// membar.gpu's CCTL.IVALL (full L1D flush) every step.
__device__ __forceinline__ void st_release_gpu(int* p, int v) {
    asm volatile("st.global.release.gpu.b32 [%0], %1;" :: "l"(p), "r"(v));
}
__device__ __forceinline__ float ldg_nc_f32(const float* p) {
    float v;
    asm volatile("ld.global.nc.f32 %0, [%1];" : "=f"(v) : "l"(p));
    return v;
}
// Ring loads: .cg bypasses L1 (no stale lines now that the per-step L1 flush
// is gone); flag acquire ordered before these by the poll + syncwarp.
__device__ __forceinline__ float4 ldg_cg_f32x4(const float* p) {
    float4 v;
    asm volatile("ld.global.cg.v4.f32 {%0, %1, %2, %3}, [%4];"
                 : "=f"(v.x), "=f"(v.y), "=f"(v.z), "=f"(v.w) : "l"(p));
    return v;
}

// ==============================================================================
// Projection GEMM:  g_P[r][n] = sum_k A[r][k] * W[n][k] + bias[n]
// 128x128 tile, BK=8, 256 threads, 8x8 microtile. Block (0,0) resets flags
// (stream order: lands before the following rec_kernel).
// ==============================================================================
__global__ __launch_bounds__(256) void proj_kernel(
    const float* __restrict__ Aext, int useO,
    const float* __restrict__ W,
    const float* __restrict__ bias,
    int K)
{
    const float* A = useO ? g_O : Aext;

    __shared__ float As[8][128];
    __shared__ float Bs[8][128];

    int tid = threadIdx.x;
    if (blockIdx.x == 0 && blockIdx.y == 0 && tid < GB * GJ) g_flags[tid] = 0;

    int m0 = blockIdx.y * 128;
    int n0 = blockIdx.x * 128;

    int lr = tid >> 1;
    int lk = (tid & 1) * 4;

    const float4* Aload = (const float4*)(A + (size_t)(m0 + lr) * K + lk);
    const float4* Wload = (const float4*)(W + (size_t)(n0 + lr) * K + lk);

    int tm = tid >> 4;
    int tn = tid & 15;

    float acc[8][8];
    #pragma unroll
    for (int i = 0; i < 8; i++)
        #pragma unroll
        for (int j = 0; j < 8; j++) acc[i][j] = 0.f;

    for (int k0 = 0; k0 < K; k0 += 8) {
        float4 av = Aload[k0 >> 2];
        float4 wv = Wload[k0 >> 2];
        As[lk + 0][lr] = av.x; As[lk + 1][lr] = av.y;
        As[lk + 2][lr] = av.z; As[lk + 3][lr] = av.w;
        Bs[lk + 0][lr] = wv.x; Bs[lk + 1][lr] = wv.y;
        Bs[lk + 2][lr] = wv.z; Bs[lk + 3][lr] = wv.w;
        __syncthreads();

        #pragma unroll
        for (int kk = 0; kk < 8; kk++) {
            float a[8], b[8];
            *(float4*)(a)     = *(const float4*)(&As[kk][tm * 8]);
            *(float4*)(a + 4) = *(const float4*)(&As[kk][tm * 8 + 4]);
            *(float4*)(b)     = *(const float4*)(&Bs[kk][tn * 8]);
            *(float4*)(b + 4) = *(const float4*)(&Bs[kk][tn * 8 + 4]);
            #pragma unroll
            for (int i = 0; i < 8; i++)
                #pragma unroll
                for (int j = 0; j < 8; j++)
                    acc[i][j] += a[i] * b[j];
        }
        __syncthreads();
    }

    float bv[8];
    #pragma unroll
    for (int j = 0; j < 8; j++) bv[j] = bias[n0 + tn * 8 + j];

    #pragma unroll
    for (int i = 0; i < 8; i++) {
        float* crow = g_P + (size_t)(m0 + tm * 8 + i) * HID + n0 + tn * 8;
        float4 v0 = make_float4(acc[i][0] + bv[0], acc[i][1] + bv[1],
                                acc[i][2] + bv[2], acc[i][3] + bv[3]);
        float4 v1 = make_float4(acc[i][4] + bv[4], acc[i][5] + bv[5],
                                acc[i][6] + bv[6], acc[i][7] + bv[7]);
        *(float4*)(crow)     = v0;
        *(float4*)(crow + 4) = v1;
    }
}

// ==============================================================================
// Persistent recurrence kernel: L2 ring + per-warp peer waits, no threadfence.
//   h_t = tanh( g_P[b][t][:] + W_hh @ h_{t-1} + b_hh )
// Grid (GJ, GB) = 128 CTAs. Warp w owns k-chunk [64w,64w+64) == j-slice of
// peer CTA w, so it waits only on flag[w], loads its 128 floats (.cg), and
// starts its dot immediately. CTA converges at the reduce barrier.
// Publish: ring STG -> bar -> tid0 release-store flag -> outbuf STG (off path).
// Safety: flag>=t+2 from a peer implies it finished reading slot t&1, so
// overwriting slot t&1 at step t+2 is safe (double buffer, monotonic flags).
// ==============================================================================
__global__ __launch_bounds__(256, 1) void rec_kernel(
    const float* __restrict__ Whh,        // [512][512]
    const float* __restrict__ h0l,        // [32][512]
    const float* __restrict__ bhh,        // [512]
    float* __restrict__ out_ext, int useO,
    float* __restrict__ hidden_out)       // [32][512]
{
    float* outbuf = useO ? g_O : out_ext;

    const int jg = blockIdx.x;            // 0..7  j-group
    const int bg = blockIdx.y;            // 0..15 batch group
    const int b0 = bg * 2;
    const int jbase = jg * 64;

    const int tid  = threadIdx.x;
    const int w    = tid >> 5;            // warp -> k-chunk / peer CTA
    const int lane = tid & 31;

    __shared__ __align__(16) float sh[8][2][64];   // [w][batch][k] staging
    __shared__ float red[8][2][64];                // [w][batch][j] partials

    // W_hh slice in registers, f32x2-packed along k.
    unsigned long long Wr0[32], Wr1[32];
    {
        const float4* r0 = (const float4*)(Whh + (size_t)(jbase + lane) * HID + w * 64);
        const float4* r1 = (const float4*)(Whh + (size_t)(jbase + lane + 32) * HID + w * 64);
        #pragma unroll
        for (int i = 0; i < 16; i++) {
            float4 v0 = r0[i];
            Wr0[2 * i]     = pack2(v0.x, v0.y);
            Wr0[2 * i + 1] = pack2(v0.z, v0.w);
            float4 v1 = r1[i];
            Wr1[2 * i]     = pack2(v1.x, v1.y);
            Wr1[2 * i + 1] = pack2(v1.z, v1.w);
        }
    }

    int*       my_flag = &g_flags[bg * GJ + jg];
    const int* w_flag  = &g_flags[bg * GJ + w];

    // Staging load mapping: lane -> (batch, 4 k-values)
    const int sb = lane >> 4;             // 0/1
    const int sk = (lane & 15) * 4;

    // Reduce mapping: tid<128 -> output (batch ob, column jl)
    const int ob = tid >> 6;
    const int jl = tid & 63;
    const float bias_r = (tid < 128) ? bhh[jbase + jl] : 0.f;
    const float* prep = g_P + ((size_t)(b0 + ob) * SEQ) * HID + jbase + jl;

    for (int t = 0; t < SEQ; t++) {
        // Pre-activation prefetch (DRAM latency overlapped with wait+dot)
        float pre_v = 0.f;
        if (tid < 128) pre_v = ldg_nc_f32(prep + (size_t)t * HID);

        // ---- per-warp acquire of this warp's k-chunk of h_{t-1} ----
        const float* src;
        if (t == 0) {
            src = h0l + (size_t)b0 * HID;
        } else {
            if (lane == 0) while (ld_acquire_gpu(w_flag) < t) { }
            __syncwarp();
            src = g_hbuf[(t - 1) & 1] + (size_t)b0 * HID;
        }
        float4 hv = ldg_cg_f32x4(src + (size_t)sb * HID + w * 64 + sk);
        *(float4*)&sh[w][sb][sk] = hv;
        __syncwarp();

        // ---- dot over this warp's 64-wide k chunk (f32x2 packed) ----
        const unsigned long long* hA = (const unsigned long long*)(&sh[w][0][0]);
        const unsigned long long* hB = (const unsigned long long*)(&sh[w][1][0]);
        unsigned long long a00 = 0ull, a01 = 0ull, a10 = 0ull, a11 = 0ull;
        #pragma unroll
        for (int kk = 0; kk < 32; kk++) {
            unsigned long long ha = hA[kk];   // LDS.64 broadcast
            unsigned long long hb = hB[kk];
            a00 = ffma2(Wr0[kk], ha, a00);
            a01 = ffma2(Wr0[kk], hb, a01);
            a10 = ffma2(Wr1[kk], ha, a10);
            a11 = ffma2(Wr1[kk], hb, a11);
        }
        red[w][0][lane]      = pairsum(a00);
        red[w][1][lane]      = pairsum(a01);
        red[w][0][lane + 32] = pairsum(a10);
        red[w][1][lane + 32] = pairsum(a11);
        __syncthreads();

        // ---- reduce 8 k-chunks, tanh ----
        float val = 0.f;
        if (tid < 128) {
            float s = pre_v + bias_r;
            #pragma unroll
            for (int ww = 0; ww < 8; ww++) s += red[ww][ob][jl];
            val = tanhf(s);
            if (t < SEQ - 1)
                g_hbuf[t & 1][(size_t)(b0 + ob) * HID + jbase + jl] = val;
        }
        __syncthreads();   // ring stores done CTA-wide before release

        if (t < SEQ - 1) {
            if (tid == 0) st_release_gpu(my_flag, t + 1);
        }

        // ---- off-critical-path DRAM stores ----
        if (tid < 128) {
            outbuf[((size_t)(b0 + ob) * SEQ + t) * HID + jbase + jl] = val;
            if (t == SEQ - 1)
                hidden_out[(size_t)(b0 + ob) * HID + jbase + jl] = val;
        }
    }
}

// ==============================================================================
extern "C" void kernel_launch(void* const* d_in, const int* in_sizes, int n_in,
                              void* d_out, int out_size)
{
    const float* x     = (const float*)d_in[0];   // [32,1024,128]
    const float* h0    = (const float*)d_in[1];   // [3,32,512]
    const float* w_ih0 = (const float*)d_in[2];   // [512,128]
    const float* w_ihs = (const float*)d_in[3];   // [2,512,512]
    const float* w_hhs = (const float*)d_in[4];   // [3,512,512]
    const float* b_ihs = (const float*)d_in[5];   // [3,512]
    const float* b_hhs = (const float*)d_in[6];   // [3,512]

    float* out    = (float*)d_out;
    float* hidden = out;                                   // [3][32][512]
    float* outseq = out + (size_t)LAYERS * BATCH * HID;    // [32*1024][512]

    dim3 pg(HID / 128, (BATCH * SEQ) / 128);               // (4, 256)
    dim3 rg(GJ, GB);                                       // (8, 16) = 128 CTAs

    // ---- layer 0 ----
    proj_kernel<<<pg, 256>>>(x, 0, w_ih0, b_ihs + 0 * HID, INDIM);
    rec_kernel<<<rg, 256>>>(w_hhs + (size_t)0 * HID * HID,
                            h0 + (size_t)0 * BATCH * HID,
                            b_hhs + 0 * HID,
                            nullptr, 1,
                            hidden + (size_t)0 * BATCH * HID);
    // ---- layer 1 ----
    proj_kernel<<<pg, 256>>>(nullptr, 1, w_ihs + (size_t)0 * HID * HID,
                             b_ihs + 1 * HID, HID);
    rec_kernel<<<rg, 256>>>(w_hhs + (size_t)1 * HID * HID,
                            h0 + (size_t)1 * BATCH * HID,
                            b_hhs + 1 * HID,
                            nullptr, 1,
                            hidden + (size_t)1 * BATCH * HID);
    // ---- layer 2 (sequence straight into d_out) ----
    proj_kernel<<<pg, 256>>>(nullptr, 1, w_ihs + (size_t)1 * HID * HID,
                             b_ihs + 2 * HID, HID);
    rec_kernel<<<rg, 256>>>(w_hhs + (size_t)2 * HID * HID,
                            h0 + (size_t)2 * BATCH * HID,
                            b_hhs + 2 * HID,
                            outseq, 0,
                            hidden + (size_t)2 * BATCH * HID);
}

// round 14
// speedup vs baseline: 2.0925x; 2.0925x over previous
#include <cuda_runtime.h>
#include <cstdint>
#include <cstddef>

// Problem constants
#define BATCH  32
#define SEQ    1024
#define INDIM  128
#define HID    512
#define LAYERS 3

// Recurrence decomposition (R2-proven): 16 batch groups (2 batches) x 8 j-groups
#define GB 16
#define GJ 8

// ---------------- device scratch (allocation-free rule) ------------------------
__device__ float g_P[(size_t)BATCH * SEQ * HID];   // pre-activations, current layer
__device__ float g_O[(size_t)BATCH * SEQ * HID];   // layer output sequence
__device__ float g_hbuf[2][BATCH * HID];           // double-buffered hidden state
__device__ int   g_flags[GB * GJ];                 // monotonic per-CTA step flags

// ---------------- PTX helpers --------------------------------------------------
__device__ __forceinline__ unsigned long long pack2(float x, float y) {
    unsigned long long r;
    asm("mov.b64 %0, {%1, %2};" : "=l"(r) : "f"(x), "f"(y));
    return r;
}
__device__ __forceinline__ unsigned long long ffma2(unsigned long long a,
                                                    unsigned long long b,
                                                    unsigned long long c) {
    unsigned long long d;
    asm("fma.rn.f32x2 %0, %1, %2, %3;" : "=l"(d) : "l"(a), "l"(b), "l"(c));
    return d;
}
__device__ __forceinline__ float pairsum(unsigned long long p) {
    unsigned lo, hi;
    asm("mov.b64 {%0, %1}, %2;" : "=r"(lo), "=r"(hi) : "l"(p));
    return __uint_as_float(lo) + __uint_as_float(hi);
}
__device__ __forceinline__ int ld_acquire_gpu(const int* p) {
    int v;
    asm volatile("ld.global.acquire.gpu.b32 %0, [%1];" : "=r"(v) : "l"(p));
    return v;
}
__device__ __forceinline__ void st_relaxed_gpu(int* p, int v) {
    asm volatile("st.global.relaxed.gpu.b32 [%0], %1;" :: "l"(p), "r"(v));
}
__device__ __forceinline__ float ldg_nc_f32(const float* p) {
    float v;
    asm volatile("ld.global.nc.f32 %0, [%1];" : "=f"(v) : "l"(p));
    return v;
}

// ==============================================================================
// Projection GEMM:  g_P[r][n] = sum_k A[r][k] * W[n][k] + bias[n]
// 128x128 tile, BK=8, 256 threads, 8x8 microtile. Block (0,0) resets the
// recurrence flags (stream order: lands before the following rec_kernel).
// ==============================================================================
__global__ __launch_bounds__(256) void proj_kernel(
    const float* __restrict__ Aext, int useO,
    const float* __restrict__ W,
    const float* __restrict__ bias,
    int K)
{
    const float* A = useO ? g_O : Aext;

    __shared__ float As[8][128];
    __shared__ float Bs[8][128];

    int tid = threadIdx.x;
    if (blockIdx.x == 0 && blockIdx.y == 0 && tid < GB * GJ) g_flags[tid] = 0;

    int m0 = blockIdx.y * 128;
    int n0 = blockIdx.x * 128;

    int lr = tid >> 1;
    int lk = (tid & 1) * 4;

    const float4* Aload = (const float4*)(A + (size_t)(m0 + lr) * K + lk);
    const float4* Wload = (const float4*)(W + (size_t)(n0 + lr) * K + lk);

    int tm = tid >> 4;
    int tn = tid & 15;

    float acc[8][8];
    #pragma unroll
    for (int i = 0; i < 8; i++)
        #pragma unroll
        for (int j = 0; j < 8; j++) acc[i][j] = 0.f;

    for (int k0 = 0; k0 < K; k0 += 8) {
        float4 av = Aload[k0 >> 2];
        float4 wv = Wload[k0 >> 2];
        As[lk + 0][lr] = av.x; As[lk + 1][lr] = av.y;
        As[lk + 2][lr] = av.z; As[lk + 3][lr] = av.w;
        Bs[lk + 0][lr] = wv.x; Bs[lk + 1][lr] = wv.y;
        Bs[lk + 2][lr] = wv.z; Bs[lk + 3][lr] = wv.w;
        __syncthreads();

        #pragma unroll
        for (int kk = 0; kk < 8; kk++) {
            float a[8], b[8];
            *(float4*)(a)     = *(const float4*)(&As[kk][tm * 8]);
            *(float4*)(a + 4) = *(const float4*)(&As[kk][tm * 8 + 4]);
            *(float4*)(b)     = *(const float4*)(&Bs[kk][tn * 8]);
            *(float4*)(b + 4) = *(const float4*)(&Bs[kk][tn * 8 + 4]);
            #pragma unroll
            for (int i = 0; i < 8; i++)
                #pragma unroll
                for (int j = 0; j < 8; j++)
                    acc[i][j] += a[i] * b[j];
        }
        __syncthreads();
    }

    float bv[8];
    #pragma unroll
    for (int j = 0; j < 8; j++) bv[j] = bias[n0 + tn * 8 + j];

    #pragma unroll
    for (int i = 0; i < 8; i++) {
        float* crow = g_P + (size_t)(m0 + tm * 8 + i) * HID + n0 + tn * 8;
        float4 v0 = make_float4(acc[i][0] + bv[0], acc[i][1] + bv[1],
                                acc[i][2] + bv[2], acc[i][3] + bv[3]);
        float4 v1 = make_float4(acc[i][4] + bv[4], acc[i][5] + bv[5],
                                acc[i][6] + bv[6], acc[i][7] + bv[7]);
        *(float4*)(crow)     = v0;
        *(float4*)(crow + 4) = v1;
    }
}

// ==============================================================================
// Persistent recurrence kernel — EXACT R2 exchange protocol:
//   gate: one warp (tid<8) polls all 8 group flags (incl. own) w/ nanosleep,
//   coop-load full h_{t-1} (plain LDG; safe because the per-step
//   __threadfence's CCTL.IVALL invalidates L1 before the next read),
//   publish: ring STG -> bar -> tid0 threadfence + relaxed flag store.
// Changes vs R2 (only these two):
//   (1) outbuf/hidden DRAM stores moved AFTER the flag release,
//   (2) dot products use fma.rn.f32x2 (h batch-major, k-pairs).
// ==============================================================================
__global__ __launch_bounds__(256, 1) void rec_kernel(
    const float* __restrict__ Whh,        // [512][512]
    const float* __restrict__ h0l,        // [32][512]
    const float* __restrict__ bhh,        // [512]
    float* __restrict__ out_ext, int useO,
    float* __restrict__ hidden_out)       // [32][512]
{
    float* outbuf = useO ? g_O : out_ext;

    const int bg = blockIdx.x & (GB - 1);   // 0..15
    const int jg = blockIdx.x >> 4;         // 0..7
    const int b0 = bg * 2;
    const int jbase = jg * 64;

    const int tid  = threadIdx.x;
    const int w    = tid >> 5;              // warp -> 64-wide k chunk
    const int lane = tid & 31;

    __shared__ __align__(16) float h_sh[2][HID];   // [batch][k], batch-major
    __shared__ float red[8][2][64];                // [k-chunk][batch][jlocal]

    // W_hh slice in registers, f32x2-packed along k:
    //   Wr0 -> row jbase+lane, Wr1 -> row jbase+lane+32
    unsigned long long Wr0[32], Wr1[32];
    {
        const float4* r0 = (const float4*)(Whh + (size_t)(jbase + lane) * HID + w * 64);
        const float4* r1 = (const float4*)(Whh + (size_t)(jbase + lane + 32) * HID + w * 64);
        #pragma unroll
        for (int i = 0; i < 16; i++) {
            float4 v0 = r0[i];
            Wr0[2 * i]     = pack2(v0.x, v0.y);
            Wr0[2 * i + 1] = pack2(v0.z, v0.w);
            float4 v1 = r1[i];
            Wr1[2 * i]     = pack2(v1.x, v1.y);
            Wr1[2 * i + 1] = pack2(v1.z, v1.w);
        }
    }

    int* my_flag = &g_flags[bg * GJ + jg];

    // Reduce mapping: tid<128 -> output (batch ob, column jl)
    const int ob = tid >> 6;
    const int jl = tid & 63;
    const float bias_r = (tid < 128) ? bhh[jbase + jl] : 0.f;
    const float* prep = g_P + ((size_t)(b0 + ob) * SEQ) * HID + jbase + jl;

    // Cooperative h load mapping: thread -> (batch, float4 of k)
    const int cb = tid >> 7;                // 0/1
    const int ck = (tid & 127) * 4;

    for (int t = 0; t < SEQ; t++) {
        // Pre-activation prefetch (DRAM latency overlapped with gate + load)
        float pre_v = 0.f;
        if (tid < 128) pre_v = ldg_nc_f32(prep + (size_t)t * HID);

        // ---- gate + cooperative load of full h_{t-1} ----
        if (t == 0) {
            float4 v = *(const float4*)(h0l + (size_t)(b0 + cb) * HID + ck);
            *(float4*)&h_sh[cb][ck] = v;
        } else {
            if (tid < GJ) {
                while (ld_acquire_gpu(&g_flags[bg * GJ + tid]) < t) __nanosleep(32);
            }
            __syncthreads();
            const float* hb = g_hbuf[(t - 1) & 1];
            float4 v = *(const float4*)(hb + (size_t)(b0 + cb) * HID + ck);
            *(float4*)&h_sh[cb][ck] = v;
        }
        __syncthreads();

        // ---- dot over this warp's 64-wide k chunk (f32x2 packed) ----
        const unsigned long long* hA = (const unsigned long long*)(&h_sh[0][w * 64]);
        const unsigned long long* hB = (const unsigned long long*)(&h_sh[1][w * 64]);
        unsigned long long a00 = 0ull, a01 = 0ull, a10 = 0ull, a11 = 0ull;
        #pragma unroll
        for (int kk = 0; kk < 32; kk++) {
            unsigned long long ha = hA[kk];   // LDS.64 broadcast
            unsigned long long hb = hB[kk];
            a00 = ffma2(Wr0[kk], ha, a00);
            a01 = ffma2(Wr0[kk], hb, a01);
            a10 = ffma2(Wr1[kk], ha, a10);
            a11 = ffma2(Wr1[kk], hb, a11);
        }
        red[w][0][lane]      = pairsum(a00);
        red[w][1][lane]      = pairsum(a01);
        red[w][0][lane + 32] = pairsum(a10);
        red[w][1][lane + 32] = pairsum(a11);
        __syncthreads();

        // ---- reduce 8 k-chunks, tanh, ring store ----
        float val = 0.f;
        if (tid < 128) {
            float s = pre_v + bias_r;
            #pragma unroll
            for (int ww = 0; ww < 8; ww++) s += red[ww][ob][jl];
            val = tanhf(s);
            if (t < SEQ - 1)
                g_hbuf[t & 1][(size_t)(b0 + ob) * HID + jbase + jl] = val;
        }
        __syncthreads();   // ring stores complete CTA-wide before release

        // ---- release (R2 protocol): fence (drains ring stores, flushes L1
        //      for next step's reads) + relaxed flag store ----
        if (t < SEQ - 1 && tid == 0) {
            __threadfence();
            st_relaxed_gpu(my_flag, t + 1);
        }

        // ---- off-critical-path DRAM stores (moved after the release) ----
        if (tid < 128) {
            outbuf[((size_t)(b0 + ob) * SEQ + t) * HID + jbase + jl] = val;
            if (t == SEQ - 1)
                hidden_out[(size_t)(b0 + ob) * HID + jbase + jl] = val;
        }
    }
}

// ==============================================================================
extern "C" void kernel_launch(void* const* d_in, const int* in_sizes, int n_in,
                              void* d_out, int out_size)
{
    const float* x     = (const float*)d_in[0];   // [32,1024,128]
    const float* h0    = (const float*)d_in[1];   // [3,32,512]
    const float* w_ih0 = (const float*)d_in[2];   // [512,128]
    const float* w_ihs = (const float*)d_in[3];   // [2,512,512]
    const float* w_hhs = (const float*)d_in[4];   // [3,512,512]
    const float* b_ihs = (const float*)d_in[5];   // [3,512]
    const float* b_hhs = (const float*)d_in[6];   // [3,512]

    float* out    = (float*)d_out;
    float* hidden = out;                                   // [3][32][512]
    float* outseq = out + (size_t)LAYERS * BATCH * HID;    // [32*1024][512]

    dim3 pg(HID / 128, (BATCH * SEQ) / 128);               // (4, 256)

    // ---- layer 0 ----
    proj_kernel<<<pg, 256>>>(x, 0, w_ih0, b_ihs + 0 * HID, INDIM);
    rec_kernel<<<GB * GJ, 256>>>(w_hhs + (size_t)0 * HID * HID,
                                 h0 + (size_t)0 * BATCH * HID,
                                 b_hhs + 0 * HID,
                                 nullptr, 1,
                                 hidden + (size_t)0 * BATCH * HID);
    // ---- layer 1 ----
    proj_kernel<<<pg, 256>>>(nullptr, 1, w_ihs + (size_t)0 * HID * HID,
                             b_ihs + 1 * HID, HID);
    rec_kernel<<<GB * GJ, 256>>>(w_hhs + (size_t)1 * HID * HID,
                                 h0 + (size_t)1 * BATCH * HID,
                                 b_hhs + 1 * HID,
                                 nullptr, 1,
                                 hidden + (size_t)1 * BATCH * HID);
    // ---- layer 2 (sequence straight into d_out) ----
    proj_kernel<<<pg, 256>>>(nullptr, 1, w_ihs + (size_t)1 * HID * HID,
                             b_ihs + 2 * HID, HID);
    rec_kernel<<<GB * GJ, 256>>>(w_hhs + (size_t)2 * HID * HID,
                                 h0 + (size_t)2 * BATCH * HID,
                                 b_hhs + 2 * HID,
                                 outseq, 0,
                                 hidden + (size_t)2 * BATCH * HID);
}